// round 15
// baseline (speedup 1.0000x reference)
#include <cuda_runtime.h>
#include <cuda_fp16.h>
#include <cstdint>

// ---------------------------------------------------------------------------
// Problem constants
// ---------------------------------------------------------------------------
#define BATCH   16
#define DDIM    1024
#define NIMG    256
#define MTOK    (BATCH * NIMG)   // 4096
#define KCODES  8192
#define TN      256
#define NTILES  (KCODES / TN)    // 32 code tiles

// GEMM tiling: fp16, block 128x256, 16 warps of 32x64, KC=64 (128B rows)
#define TM 128
#define KC 64
#define NCHUNK (DDIM / KC)       // 16
#define NSTAGE 3
#define GTHREADS 512

// Dynamic smem layout
#define OFF_A  0
#define OFF_B  16384
#define STAGE  49152                          // 16KB A + 32KB B
#define ES_OFF   (NSTAGE * STAGE)             // 147456, 256 floats
#define TOP1_OFF (ES_OFF + 1024)              // u64 [128][4]
#define TOP2_OFF (TOP1_OFF + 4096)
#define DYN_SMEM (TOP2_OFF + 4096)            // 156672

#define EPS 0.25f

// convert grid split: cb blocks FIRST (longest work first -> better packing)
#define CBBLOCKS (KCODES / 8)                 // 1024
#define XBLOCKS 2048                          // 8 nt x 16 ct x 16 b

// ---------------------------------------------------------------------------
// Global scratch (allocation-free rule: __device__ globals)
// ---------------------------------------------------------------------------
__device__ __half  g_A[MTOK * DDIM];
__device__ __half  g_B[KCODES * DDIM];
__device__ float   g_esq[KCODES];
// interleaved: [token][tile][{top1, top2}]
__device__ unsigned long long g_cand[MTOK * NTILES * 2];

// ---------------------------------------------------------------------------
// Helpers
// ---------------------------------------------------------------------------
__device__ __forceinline__ uint32_t smem_u32(const void* p) {
    uint32_t a;
    asm("{ .reg .u64 t; cvta.to.shared.u64 t, %1; cvt.u32.u64 %0, t; }" : "=r"(a) : "l"(p));
    return a;
}

#define CP_ASYNC16(dst, src) \
    asm volatile("cp.async.cg.shared.global [%0], [%1], 16;\n" :: "r"(dst), "l"(src))
#define CP_COMMIT() asm volatile("cp.async.commit_group;\n" ::: "memory")

#define LDSM4(r0, r1, r2, r3, addr)                                         \
    asm volatile("ldmatrix.sync.aligned.m8n8.x4.shared.b16 {%0,%1,%2,%3}, [%4];" \
                 : "=r"(r0), "=r"(r1), "=r"(r2), "=r"(r3) : "r"(addr))

#define MMA16816(acc, a, b0, b1)                                            \
    asm volatile("mma.sync.aligned.m16n8k16.row.col.f32.f16.f16.f32 "       \
                 "{%0,%1,%2,%3}, {%4,%5,%6,%7}, {%8,%9}, {%0,%1,%2,%3};"    \
                 : "+f"((acc)[0]), "+f"((acc)[1]), "+f"((acc)[2]), "+f"((acc)[3]) \
                 : "r"((a)[0]), "r"((a)[1]), "r"((a)[2]), "r"((a)[3]),      \
                   "r"(b0), "r"(b1))

__device__ __forceinline__ unsigned long long pack_key(float d, int k) {
    unsigned u = __float_as_uint(d);
    u = (u & 0x80000000u) ? ~u : (u | 0x80000000u);
    return ((unsigned long long)u << 32) | (unsigned)k;
}
__device__ __forceinline__ float unpack_key_d(unsigned long long key) {
    unsigned u = (unsigned)(key >> 32);
    u = (u & 0x80000000u) ? (u ^ 0x80000000u) : ~u;
    return __uint_as_float(u);
}
__device__ __forceinline__ void upd_top2(unsigned long long& k1, unsigned long long& k2,
                                         unsigned long long key) {
    if (key < k1) { k2 = k1; k1 = key; }
    else if (key < k2) { k2 = key; }
}
__device__ __forceinline__ void merge_top2(unsigned long long& k1, unsigned long long& k2,
                                           unsigned long long o1, unsigned long long o2) {
    if (o1 < k1) { k2 = (k1 < o2) ? k1 : o2; k1 = o1; }
    else if (o1 < k2) { k2 = o1; }
}

// row x 128-byte tile, 16B chunk swizzle: conflict-free for ldmatrix and cp.async
__device__ __forceinline__ uint32_t sw_off128(int row, int chunk) {
    return (uint32_t)(row * 128 + ((chunk ^ (row & 7)) << 4));
}

// ---------------------------------------------------------------------------
// Fused prepass (unchanged from R14 best).
// ---------------------------------------------------------------------------
__global__ void convert_all_kernel(const float* __restrict__ x, const float* __restrict__ cb) {
    const int bid = blockIdx.x;
    const int tx = threadIdx.x, ty = threadIdx.y;
    const int tid = ty * 32 + tx;

    if (bid < CBBLOCKS) {
        const int wid = tid >> 5, lane = tid & 31;
        const int gw = bid * 8 + wid;
        const float4* row = reinterpret_cast<const float4*>(cb + (size_t)gw * DDIM);
        float4 v[8];
        #pragma unroll
        for (int w = 0; w < 8; w++) v[w] = row[lane + w * 32];
        float s = 0.f;
        #pragma unroll
        for (int w = 0; w < 8; w++) {
            s += v[w].x * v[w].x + v[w].y * v[w].y + v[w].z * v[w].z + v[w].w * v[w].w;
            __half2 h01 = __floats2half2_rn(v[w].x, v[w].y);
            __half2 h23 = __floats2half2_rn(v[w].z, v[w].w);
            uint2 pk;
            pk.x = *reinterpret_cast<uint32_t*>(&h01);
            pk.y = *reinterpret_cast<uint32_t*>(&h23);
            *reinterpret_cast<uint2*>(&g_B[(size_t)gw * DDIM + (lane + w * 32) * 4]) = pk;
        }
        #pragma unroll
        for (int o = 16; o > 0; o >>= 1) s += __shfl_xor_sync(0xFFFFFFFFu, s, o);
        if (lane == 0) g_esq[gw] = s;
    } else {
        __shared__ float tile[64][33];
        const int bx = bid - CBBLOCKS;
        const int nt = bx & 7;
        const int ct = (bx >> 3) & 15;
        const int b = bx >> 7;
        const float* src = x + (size_t)b * (DDIM * NIMG) + (size_t)(ct * 64) * NIMG + nt * 32;
        float rv[8];
        #pragma unroll
        for (int r = 0; r < 8; r++) rv[r] = src[(size_t)(ty + 8 * r) * NIMG + tx];
        #pragma unroll
        for (int r = 0; r < 8; r++) tile[ty + 8 * r][tx] = rv[r];
        __syncthreads();
        const int m0 = b * NIMG + nt * 32;
        const int lane = tx;
        #pragma unroll
        for (int it = 0; it < 4; it++) {
            int j = ty + 8 * it;
            float v0 = tile[2 * lane][j];
            float v1 = tile[2 * lane + 1][j];
            __half2 h = __floats2half2_rn(v0, v1);
            *reinterpret_cast<__half2*>(
                &g_A[(size_t)(m0 + j) * DDIM + ct * 64 + 2 * lane]) = h;
        }
    }
}

// ---------------------------------------------------------------------------
// Main GEMM: block 128x256, 512 threads, 16 warps of the proven 32x64 tile.
// Same warps/SM (16) as the 2x256 config; halved A L2 traffic + epilogues.
// ---------------------------------------------------------------------------
__device__ __forceinline__ void load_chunk(uint32_t st, int m0, int k0, int c0, int tid) {
    const __half* aa = g_A;
    const __half* bb = g_B;
    #pragma unroll
    for (int i = 0; i < 2; i++) {          // A: 128 rows x 8 chunks
        int vid = tid + i * GTHREADS;
        int r = vid >> 3, c = vid & 7;
        CP_ASYNC16(st + OFF_A + sw_off128(r, c), aa + (size_t)(m0 + r) * DDIM + c0 + c * 8);
    }
    #pragma unroll
    for (int i = 0; i < 4; i++) {          // B: 256 rows x 8 chunks
        int vid = tid + i * GTHREADS;
        int r = vid >> 3, c = vid & 7;
        CP_ASYNC16(st + OFF_B + sw_off128(r, c), bb + (size_t)(k0 + r) * DDIM + c0 + c * 8);
    }
    CP_COMMIT();
}

__global__ __launch_bounds__(GTHREADS, 1)
void gemm_argmin_kernel() {
    extern __shared__ char dynsm[];
    const int tid = threadIdx.x;
    const int lane = tid & 31;
    const int wid = tid >> 5;
    const int wr = wid & 3;              // M band (32 rows), 0..3
    const int wc = wid >> 2;             // N band (64 cols), 0..3
    const int bx = blockIdx.x;           // code tile
    const int m0 = blockIdx.y * TM;
    const int k0 = bx * TN;

    const uint32_t smb = smem_u32(dynsm);
    float* s_es = (float*)(dynsm + ES_OFF);
    unsigned long long* s_top1 = (unsigned long long*)(dynsm + TOP1_OFF);
    unsigned long long* s_top2 = (unsigned long long*)(dynsm + TOP2_OFF);

    if (tid < TN) s_es[tid] = g_esq[k0 + tid];

    const int hi = lane >> 4;            // chunk parity within k-step
    uint32_t baseA[2]; int selA[2];
    #pragma unroll
    for (int mt = 0; mt < 2; mt++) {
        int row = wr * 32 + mt * 16 + (lane & 15);
        baseA[mt] = (uint32_t)(row * 128);
        selA[mt] = row & 7;
    }
    uint32_t baseB[4]; int selB[4];
    #pragma unroll
    for (int g = 0; g < 4; g++) {
        int row = wc * 64 + g * 16 + (lane & 15);
        baseB[g] = (uint32_t)(row * 128);
        selB[g] = row & 7;
    }

    float acc[2][8][4];
    #pragma unroll
    for (int mt = 0; mt < 2; mt++)
        #pragma unroll
        for (int nt = 0; nt < 8; nt++)
            #pragma unroll
            for (int j = 0; j < 4; j++) acc[mt][nt][j] = 0.f;

    load_chunk(smb + 0 * STAGE, m0, k0, 0, tid);
    load_chunk(smb + 1 * STAGE, m0, k0, KC, tid);

    int sidx = 0, widx = 2;
    for (int i = 0; i < NCHUNK; i++) {
        if (i + 1 < NCHUNK) { asm volatile("cp.async.wait_group 1;\n" ::: "memory"); }
        else               { asm volatile("cp.async.wait_group 0;\n" ::: "memory"); }
        __syncthreads();
        if (i + 2 < NCHUNK) {
            load_chunk(smb + widx * STAGE, m0, k0, (i + 2) * KC, tid);
            widx = (widx == NSTAGE - 1) ? 0 : widx + 1;
        }

        const uint32_t st = smb + sidx * STAGE;
        #pragma unroll
        for (int ks = 0; ks < 4; ks++) {
            const int ck = 2 * ks + hi;
            uint32_t af[2][4];
            #pragma unroll
            for (int mt = 0; mt < 2; mt++)
                LDSM4(af[mt][0], af[mt][1], af[mt][2], af[mt][3],
                      st + OFF_A + baseA[mt] + ((ck ^ selA[mt]) << 4));
            #pragma unroll
            for (int g = 0; g < 4; g++) {
                uint32_t bf[4];
                LDSM4(bf[0], bf[1], bf[2], bf[3],
                      st + OFF_B + baseB[g] + ((ck ^ selB[g]) << 4));
                #pragma unroll
                for (int mt = 0; mt < 2; mt++) {
                    MMA16816(acc[mt][2 * g],     af[mt], bf[0], bf[2]);
                    MMA16816(acc[mt][2 * g + 1], af[mt], bf[1], bf[3]);
                }
            }
        }
        sidx = (sidx == NSTAGE - 1) ? 0 : sidx + 1;
    }

    // ---- epilogue: dist = e_sq - 2*cross, per-row top-2 over this 256-code tile
    unsigned long long t1[4], t2[4];   // [mt*2 + rhalf]
    #pragma unroll
    for (int i = 0; i < 4; i++) { t1[i] = ~0ULL; t2[i] = ~0ULL; }

    #pragma unroll
    for (int nt = 0; nt < 8; nt++) {
        int cl = wc * 64 + nt * 8 + (lane & 3) * 2;
        float e0 = s_es[cl], e1 = s_es[cl + 1];
        int kg = k0 + cl;
        #pragma unroll
        for (int mt = 0; mt < 2; mt++) {
            upd_top2(t1[mt * 2], t2[mt * 2], pack_key(e0 - 2.f * acc[mt][nt][0], kg));
            upd_top2(t1[mt * 2], t2[mt * 2], pack_key(e1 - 2.f * acc[mt][nt][1], kg + 1));
            upd_top2(t1[mt * 2 + 1], t2[mt * 2 + 1], pack_key(e0 - 2.f * acc[mt][nt][2], kg));
            upd_top2(t1[mt * 2 + 1], t2[mt * 2 + 1], pack_key(e1 - 2.f * acc[mt][nt][3], kg + 1));
        }
    }
    #pragma unroll
    for (int i = 0; i < 4; i++) {
        #pragma unroll
        for (int off = 1; off <= 2; off <<= 1) {
            unsigned long long o1 = __shfl_xor_sync(0xFFFFFFFFu, t1[i], off);
            unsigned long long o2 = __shfl_xor_sync(0xFFFFFFFFu, t2[i], off);
            merge_top2(t1[i], t2[i], o1, o2);
        }
    }
    if ((lane & 3) == 0) {
        #pragma unroll
        for (int i = 0; i < 4; i++) {
            int mt = i >> 1, rh = i & 1;
            int rl = wr * 32 + mt * 16 + (lane >> 2) + rh * 8;
            s_top1[rl * 4 + wc] = t1[i];
            s_top2[rl * 4 + wc] = t2[i];
        }
    }
    __syncthreads();
    if (tid < TM) {
        unsigned long long k1 = s_top1[tid * 4], k2 = s_top2[tid * 4];
        #pragma unroll
        for (int w = 1; w < 4; w++)
            merge_top2(k1, k2, s_top1[tid * 4 + w], s_top2[tid * 4 + w]);
        ulonglong2 pr; pr.x = k1; pr.y = k2;
        *reinterpret_cast<ulonglong2*>(
            &g_cand[((size_t)(m0 + tid) * NTILES + bx) * 2]) = pr;
    }
}

// ---------------------------------------------------------------------------
// Fused rescore + gather: 512 blocks x 256 threads; 8 tokens per block.
// NTILES=32 -> 64 keys/token, one 16B load per lane.
// ---------------------------------------------------------------------------
__global__ __launch_bounds__(256)
void rescore_gather_kernel(const float* __restrict__ x, const float* __restrict__ cb,
                           const float* __restrict__ values, float* __restrict__ out) {
    __shared__ __align__(16) float buf[8][1036];   // 1036 % 32 == 12: conflict-free
    __shared__ int s_idx[8];
    const int warp = threadIdx.x >> 5;
    const int lane = threadIdx.x & 31;
    const int mb = blockIdx.x * 8;                 // 8 consecutive tokens, same batch
    const int b = mb >> 8;
    const int n0 = mb & 255;
    const int m = mb + warp;

    // ---- issue candidate loads first (latency overlapped with x staging)
    const ulonglong2* cp = reinterpret_cast<const ulonglong2*>(&g_cand[(size_t)m * NTILES * 2]);
    ulonglong2 pa = cp[lane];                      // lane -> tile, {top1, top2}

    // ---- stage x[b][:, n0:n0+8] -> buf[j][c]
    const float* xb = x + (size_t)b * (DDIM * NIMG) + n0;
    #pragma unroll
    for (int i = 0; i < 32; i++) {
        int L = threadIdx.x + i * 256;             // 0..8191
        int c = L >> 3, j = L & 7;
        buf[j][c] = xb[(size_t)c * NIMG + j];
    }

    // ---- key min-reduce (overlaps staging stores; no buf dependence yet)
    unsigned long long k[2] = {pa.x, pa.y};
    unsigned long long mn = (k[1] < k[0]) ? k[1] : k[0];
    #pragma unroll
    for (int o = 16; o > 0; o >>= 1) {
        unsigned long long t = __shfl_xor_sync(0xFFFFFFFFu, mn, o);
        if (t < mn) mn = t;
    }
    const float thr = unpack_key_d(mn) + EPS;
    __syncthreads();

    float bd = 3.4e38f;
    int bk = 0x7FFFFFFF;
    const float4* a4 = reinterpret_cast<const float4*>(&buf[warp][0]);

    #pragma unroll
    for (int s = 0; s < 2; s++) {
        unsigned msk = __ballot_sync(0xFFFFFFFFu, unpack_key_d(k[s]) <= thr);
        while (msk) {
            int src = __ffs(msk) - 1;
            msk &= msk - 1;
            int kk = (int)(__shfl_sync(0xFFFFFFFFu, k[s], src) & 0xFFFFFFFFULL);
            const float es = g_esq[kk];
            const float4* e4 = reinterpret_cast<const float4*>(cb + (size_t)kk * DDIM);
            float p = 0.f;
            #pragma unroll
            for (int w8 = 0; w8 < 8; w8++) {
                float4 a = a4[lane + w8 * 32];
                float4 e = e4[lane + w8 * 32];
                p += a.x * e.x + a.y * e.y + a.z * e.z + a.w * e.w;
            }
            #pragma unroll
            for (int o = 16; o > 0; o >>= 1) p += __shfl_xor_sync(0xFFFFFFFFu, p, o);
            float d = es - 2.f * p;
            if (d < bd || (d == bd && kk < bk)) { bd = d; bk = kk; }
        }
    }
    if (lane == 0) s_idx[warp] = bk;
    __syncthreads();                               // all rescore reads of buf done

    // ---- gather: warp w stages values[idx[w]] (coalesced), overwriting buf
    {
        const float4* v4 = reinterpret_cast<const float4*>(values + (size_t)s_idx[warp] * DDIM);
        float4* d4 = reinterpret_cast<float4*>(&buf[warp][0]);
        #pragma unroll
        for (int w8 = 0; w8 < 8; w8++) d4[lane + w8 * 32] = v4[lane + w8 * 32];
    }
    __syncthreads();

    // ---- transposed write: out[b][c][n0+j] = buf[j][c]
    float* ob = out + (size_t)b * (DDIM * NIMG) + n0;
    #pragma unroll
    for (int i = 0; i < 32; i++) {
        int L = threadIdx.x + i * 256;
        int c = L >> 3, j = L & 7;
        ob[(size_t)c * NIMG + j] = buf[j][c];
    }
}

// ---------------------------------------------------------------------------
extern "C" void kernel_launch(void* const* d_in, const int* in_sizes, int n_in,
                              void* d_out, int out_size) {
    const float* x      = (const float*)d_in[0];
    const float* cb     = (const float*)d_in[1];
    const float* values = (const float*)d_in[2];
    float* out          = (float*)d_out;

    static int attr_set = 0;
    if (!attr_set) {
        cudaFuncSetAttribute(gemm_argmin_kernel,
                             cudaFuncAttributeMaxDynamicSharedMemorySize, DYN_SMEM);
        attr_set = 1;
    }

    convert_all_kernel<<<CBBLOCKS + XBLOCKS, dim3(32, 8)>>>(x, cb);

    gemm_argmin_kernel<<<dim3(KCODES / TN, MTOK / TM), GTHREADS, DYN_SMEM>>>();

    rescore_gather_kernel<<<MTOK / 8, 256>>>(x, cb, values, out);
}

// round 16
// speedup vs baseline: 1.0568x; 1.0568x over previous
#include <cuda_runtime.h>
#include <cuda_fp16.h>
#include <cstdint>

// ---------------------------------------------------------------------------
// Problem constants
// ---------------------------------------------------------------------------
#define BATCH   16
#define DDIM    1024
#define NIMG    256
#define MTOK    (BATCH * NIMG)   // 4096
#define KCODES  8192
#define NTILES  (KCODES / 128)   // 64 code tiles

// GEMM tiling: fp16, block 128x128, warp 32x64, KC=64 channels (128B rows)
#define TM 128
#define TN 128
#define KC 64
#define NCHUNK (DDIM / KC)       // 16
#define NSTAGE 3

// Dynamic smem layout
#define OFF_A  0
#define OFF_B  16384
#define STAGE  32768
#define ES_OFF   (NSTAGE * STAGE)            // 98304, 128 floats
#define TOP1_OFF (ES_OFF + 512)              // u64 [128][2]
#define TOP2_OFF (TOP1_OFF + 2048)
#define DYN_SMEM (TOP2_OFF + 2048)           // 102912

#define EPS 0.25f

// convert grid split: cb blocks FIRST (longest work first -> better packing)
#define CBBLOCKS (KCODES / 8)                 // 1024
#define XBLOCKS 2048                          // 8 nt x 16 ct x 16 b

// ---------------------------------------------------------------------------
// Global scratch (allocation-free rule: __device__ globals)
// ---------------------------------------------------------------------------
__device__ __half  g_A[MTOK * DDIM];
__device__ __half  g_B[KCODES * DDIM];
__device__ float   g_esq[KCODES];
// interleaved: [token][tile][{top1, top2}]
__device__ unsigned long long g_cand[MTOK * NTILES * 2];

// ---------------------------------------------------------------------------
// Helpers
// ---------------------------------------------------------------------------
__device__ __forceinline__ uint32_t smem_u32(const void* p) {
    uint32_t a;
    asm("{ .reg .u64 t; cvta.to.shared.u64 t, %1; cvt.u32.u64 %0, t; }" : "=r"(a) : "l"(p));
    return a;
}

#define CP_ASYNC16(dst, src) \
    asm volatile("cp.async.cg.shared.global [%0], [%1], 16;\n" :: "r"(dst), "l"(src))
#define CP_COMMIT() asm volatile("cp.async.commit_group;\n" ::: "memory")

#define LDSM4(r0, r1, r2, r3, addr)                                         \
    asm volatile("ldmatrix.sync.aligned.m8n8.x4.shared.b16 {%0,%1,%2,%3}, [%4];" \
                 : "=r"(r0), "=r"(r1), "=r"(r2), "=r"(r3) : "r"(addr))

#define MMA16816(acc, a, b0, b1)                                            \
    asm volatile("mma.sync.aligned.m16n8k16.row.col.f32.f16.f16.f32 "       \
                 "{%0,%1,%2,%3}, {%4,%5,%6,%7}, {%8,%9}, {%0,%1,%2,%3};"    \
                 : "+f"((acc)[0]), "+f"((acc)[1]), "+f"((acc)[2]), "+f"((acc)[3]) \
                 : "r"((a)[0]), "r"((a)[1]), "r"((a)[2]), "r"((a)[3]),      \
                   "r"(b0), "r"(b1))

__device__ __forceinline__ unsigned long long pack_key(float d, int k) {
    unsigned u = __float_as_uint(d);
    u = (u & 0x80000000u) ? ~u : (u | 0x80000000u);
    return ((unsigned long long)u << 32) | (unsigned)k;
}
__device__ __forceinline__ float unpack_key_d(unsigned long long key) {
    unsigned u = (unsigned)(key >> 32);
    u = (u & 0x80000000u) ? (u ^ 0x80000000u) : ~u;
    return __uint_as_float(u);
}
__device__ __forceinline__ void upd_top2(unsigned long long& k1, unsigned long long& k2,
                                         unsigned long long key) {
    if (key < k1) { k2 = k1; k1 = key; }
    else if (key < k2) { k2 = key; }
}
__device__ __forceinline__ void merge_top2(unsigned long long& k1, unsigned long long& k2,
                                           unsigned long long o1, unsigned long long o2) {
    if (o1 < k1) { k2 = (k1 < o2) ? k1 : o2; k1 = o1; }
    else if (o1 < k2) { k2 = o1; }
}

// 128-row x 128-byte tile, 16B chunk swizzle: conflict-free for ldmatrix and cp.async
__device__ __forceinline__ uint32_t sw_off128(int row, int chunk) {
    return (uint32_t)(row * 128 + ((chunk ^ (row & 7)) << 4));
}

// ---------------------------------------------------------------------------
// Fused prepass (R14 champion, unchanged).
// ---------------------------------------------------------------------------
__global__ void convert_all_kernel(const float* __restrict__ x, const float* __restrict__ cb) {
    const int bid = blockIdx.x;
    const int tx = threadIdx.x, ty = threadIdx.y;
    const int tid = ty * 32 + tx;

    if (bid < CBBLOCKS) {
        const int wid = tid >> 5, lane = tid & 31;
        const int gw = bid * 8 + wid;
        const float4* row = reinterpret_cast<const float4*>(cb + (size_t)gw * DDIM);
        float4 v[8];
        #pragma unroll
        for (int w = 0; w < 8; w++) v[w] = row[lane + w * 32];
        float s = 0.f;
        #pragma unroll
        for (int w = 0; w < 8; w++) {
            s += v[w].x * v[w].x + v[w].y * v[w].y + v[w].z * v[w].z + v[w].w * v[w].w;
            __half2 h01 = __floats2half2_rn(v[w].x, v[w].y);
            __half2 h23 = __floats2half2_rn(v[w].z, v[w].w);
            uint2 pk;
            pk.x = *reinterpret_cast<uint32_t*>(&h01);
            pk.y = *reinterpret_cast<uint32_t*>(&h23);
            *reinterpret_cast<uint2*>(&g_B[(size_t)gw * DDIM + (lane + w * 32) * 4]) = pk;
        }
        #pragma unroll
        for (int o = 16; o > 0; o >>= 1) s += __shfl_xor_sync(0xFFFFFFFFu, s, o);
        if (lane == 0) g_esq[gw] = s;
    } else {
        __shared__ float tile[64][33];
        const int bx = bid - CBBLOCKS;
        const int nt = bx & 7;
        const int ct = (bx >> 3) & 15;
        const int b = bx >> 7;
        const float* src = x + (size_t)b * (DDIM * NIMG) + (size_t)(ct * 64) * NIMG + nt * 32;
        float rv[8];
        #pragma unroll
        for (int r = 0; r < 8; r++) rv[r] = src[(size_t)(ty + 8 * r) * NIMG + tx];
        #pragma unroll
        for (int r = 0; r < 8; r++) tile[ty + 8 * r][tx] = rv[r];
        __syncthreads();
        const int m0 = b * NIMG + nt * 32;
        const int lane = tx;
        #pragma unroll
        for (int it = 0; it < 4; it++) {
            int j = ty + 8 * it;
            float v0 = tile[2 * lane][j];
            float v1 = tile[2 * lane + 1][j];
            __half2 h = __floats2half2_rn(v0, v1);
            *reinterpret_cast<__half2*>(
                &g_A[(size_t)(m0 + j) * DDIM + ct * 64 + 2 * lane]) = h;
        }
    }
}

// ---------------------------------------------------------------------------
// Main GEMM (R14 champion: 32x64 warp tiles, 2 CTAs/SM) + PDL trigger.
// ---------------------------------------------------------------------------
__device__ __forceinline__ void load_chunk(uint32_t st, int m0, int k0, int c0, int tid) {
    const __half* aa = g_A;
    const __half* bb = g_B;
    #pragma unroll
    for (int i = 0; i < 4; i++) {
        int vid = tid + i * 256;           // 0..1023 covers 128 rows x 8 x 16B
        int r = vid >> 3, c = vid & 7;
        uint32_t off = sw_off128(r, c);
        CP_ASYNC16(st + OFF_A + off, aa + (size_t)(m0 + r) * DDIM + c0 + c * 8);
        CP_ASYNC16(st + OFF_B + off, bb + (size_t)(k0 + r) * DDIM + c0 + c * 8);
    }
    CP_COMMIT();
}

__global__ __launch_bounds__(256, 2)
void gemm_argmin_kernel() {
    extern __shared__ char dynsm[];
    const int tid = threadIdx.x;
    const int lane = tid & 31;
    const int wid = tid >> 5;
    const int wr = wid & 3;              // M band (32 rows)
    const int wc = wid >> 2;             // N band (64 cols)
    const int bx = blockIdx.x;           // code tile
    const int m0 = blockIdx.y * TM;
    const int k0 = bx * TN;

    const uint32_t smb = smem_u32(dynsm);
    float* s_es = (float*)(dynsm + ES_OFF);
    unsigned long long* s_top1 = (unsigned long long*)(dynsm + TOP1_OFF);
    unsigned long long* s_top2 = (unsigned long long*)(dynsm + TOP2_OFF);

    if (tid < TN) s_es[tid] = g_esq[k0 + tid];

    // allow the dependent (rescore) grid to begin launching; it waits on
    // griddepcontrol.wait before reading anything we write.
    asm volatile("griddepcontrol.launch_dependents;" ::: "memory");

    const int hi = lane >> 4;            // chunk parity within k-step
    uint32_t baseA[2]; int selA[2];
    #pragma unroll
    for (int mt = 0; mt < 2; mt++) {
        int row = wr * 32 + mt * 16 + (lane & 15);
        baseA[mt] = (uint32_t)(row * 128);
        selA[mt] = row & 7;
    }
    uint32_t baseB[4]; int selB[4];
    #pragma unroll
    for (int g = 0; g < 4; g++) {
        int row = wc * 64 + g * 16 + (lane & 15);
        baseB[g] = (uint32_t)(row * 128);
        selB[g] = row & 7;
    }

    float acc[2][8][4];
    #pragma unroll
    for (int mt = 0; mt < 2; mt++)
        #pragma unroll
        for (int nt = 0; nt < 8; nt++)
            #pragma unroll
            for (int j = 0; j < 4; j++) acc[mt][nt][j] = 0.f;

    load_chunk(smb + 0 * STAGE, m0, k0, 0, tid);
    load_chunk(smb + 1 * STAGE, m0, k0, KC, tid);

    int sidx = 0, widx = 2;
    for (int i = 0; i < NCHUNK; i++) {
        // chunk i must be complete; on the last iteration chunk i is itself
        // the most recent pending group, so wait for ALL.
        if (i + 1 < NCHUNK) { asm volatile("cp.async.wait_group 1;\n" ::: "memory"); }
        else               { asm volatile("cp.async.wait_group 0;\n" ::: "memory"); }
        __syncthreads();
        // Prefetch chunk i+2 into the stage consumed in iteration i-1
        // (protected by the sync above). Single barrier per iteration.
        if (i + 2 < NCHUNK) {
            load_chunk(smb + widx * STAGE, m0, k0, (i + 2) * KC, tid);
            widx = (widx == NSTAGE - 1) ? 0 : widx + 1;
        }

        const uint32_t st = smb + sidx * STAGE;
        #pragma unroll
        for (int ks = 0; ks < 4; ks++) {
            const int ck = 2 * ks + hi;
            uint32_t af[2][4];
            #pragma unroll
            for (int mt = 0; mt < 2; mt++)
                LDSM4(af[mt][0], af[mt][1], af[mt][2], af[mt][3],
                      st + OFF_A + baseA[mt] + ((ck ^ selA[mt]) << 4));
            #pragma unroll
            for (int g = 0; g < 4; g++) {
                uint32_t bf[4];
                LDSM4(bf[0], bf[1], bf[2], bf[3],
                      st + OFF_B + baseB[g] + ((ck ^ selB[g]) << 4));
                #pragma unroll
                for (int mt = 0; mt < 2; mt++) {
                    MMA16816(acc[mt][2 * g],     af[mt], bf[0], bf[2]);
                    MMA16816(acc[mt][2 * g + 1], af[mt], bf[1], bf[3]);
                }
            }
        }
        sidx = (sidx == NSTAGE - 1) ? 0 : sidx + 1;
    }

    // ---- epilogue: dist = e_sq - 2*cross, per-row top-2 over this 128-code tile
    unsigned long long t1[4], t2[4];   // [mt*2 + rhalf]
    #pragma unroll
    for (int i = 0; i < 4; i++) { t1[i] = ~0ULL; t2[i] = ~0ULL; }

    #pragma unroll
    for (int nt = 0; nt < 8; nt++) {
        int cl = wc * 64 + nt * 8 + (lane & 3) * 2;
        float e0 = s_es[cl], e1 = s_es[cl + 1];
        int kg = k0 + cl;
        #pragma unroll
        for (int mt = 0; mt < 2; mt++) {
            upd_top2(t1[mt * 2], t2[mt * 2], pack_key(e0 - 2.f * acc[mt][nt][0], kg));
            upd_top2(t1[mt * 2], t2[mt * 2], pack_key(e1 - 2.f * acc[mt][nt][1], kg + 1));
            upd_top2(t1[mt * 2 + 1], t2[mt * 2 + 1], pack_key(e0 - 2.f * acc[mt][nt][2], kg));
            upd_top2(t1[mt * 2 + 1], t2[mt * 2 + 1], pack_key(e1 - 2.f * acc[mt][nt][3], kg + 1));
        }
    }
    #pragma unroll
    for (int i = 0; i < 4; i++) {
        #pragma unroll
        for (int off = 1; off <= 2; off <<= 1) {
            unsigned long long o1 = __shfl_xor_sync(0xFFFFFFFFu, t1[i], off);
            unsigned long long o2 = __shfl_xor_sync(0xFFFFFFFFu, t2[i], off);
            merge_top2(t1[i], t2[i], o1, o2);
        }
    }
    if ((lane & 3) == 0) {
        #pragma unroll
        for (int i = 0; i < 4; i++) {
            int mt = i >> 1, rh = i & 1;
            int rl = wr * 32 + mt * 16 + (lane >> 2) + rh * 8;
            s_top1[rl * 2 + wc] = t1[i];
            s_top2[rl * 2 + wc] = t2[i];
        }
    }
    __syncthreads();
    if (tid < TM) {
        unsigned long long k1 = s_top1[tid * 2], k2 = s_top2[tid * 2];
        merge_top2(k1, k2, s_top1[tid * 2 + 1], s_top2[tid * 2 + 1]);
        // single 16B store of {top1, top2}
        ulonglong2 pr; pr.x = k1; pr.y = k2;
        *reinterpret_cast<ulonglong2*>(
            &g_cand[((size_t)(m0 + tid) * NTILES + bx) * 2]) = pr;
    }
}

// ---------------------------------------------------------------------------
// Fused rescore + gather with PDL: stages x (GEMM-independent) BEFORE
// griddepcontrol.wait, so staging overlaps the GEMM tail wave.
// ---------------------------------------------------------------------------
__global__ __launch_bounds__(256)
void rescore_gather_kernel(const float* __restrict__ x, const float* __restrict__ cb,
                           const float* __restrict__ values, float* __restrict__ out) {
    __shared__ __align__(16) float buf[8][1036];   // 1036 % 32 == 12: conflict-free
    __shared__ int s_idx[8];
    const int warp = threadIdx.x >> 5;
    const int lane = threadIdx.x & 31;
    const int mb = blockIdx.x * 8;                 // 8 consecutive tokens, same batch
    const int b = mb >> 8;
    const int n0 = mb & 255;
    const int m = mb + warp;

    // ---- stage x[b][:, n0:n0+8] -> buf[j][c]  (independent of the GEMM)
    const float* xb = x + (size_t)b * (DDIM * NIMG) + n0;
    #pragma unroll
    for (int i = 0; i < 32; i++) {
        int L = threadIdx.x + i * 256;             // 0..8191
        int c = L >> 3, j = L & 7;
        buf[j][c] = xb[(size_t)c * NIMG + j];
    }

    // ---- wait for the GEMM grid's writes (g_cand) to be visible
    asm volatile("griddepcontrol.wait;" ::: "memory");

    const ulonglong2* cp = reinterpret_cast<const ulonglong2*>(&g_cand[(size_t)m * NTILES * 2]);
    ulonglong2 pa = cp[lane];
    ulonglong2 pb = cp[lane + 32];

    unsigned long long k[4] = {pa.x, pb.x, pa.y, pb.y};
    unsigned long long mn = k[0];
    if (k[1] < mn) mn = k[1];
    if (k[2] < mn) mn = k[2];
    if (k[3] < mn) mn = k[3];
    #pragma unroll
    for (int o = 16; o > 0; o >>= 1) {
        unsigned long long t = __shfl_xor_sync(0xFFFFFFFFu, mn, o);
        if (t < mn) mn = t;
    }
    const float thr = unpack_key_d(mn) + EPS;
    __syncthreads();

    float bd = 3.4e38f;
    int bk = 0x7FFFFFFF;
    const float4* a4 = reinterpret_cast<const float4*>(&buf[warp][0]);

    #pragma unroll
    for (int s = 0; s < 4; s++) {
        unsigned msk = __ballot_sync(0xFFFFFFFFu, unpack_key_d(k[s]) <= thr);
        while (msk) {
            int src = __ffs(msk) - 1;
            msk &= msk - 1;
            int kk = (int)(__shfl_sync(0xFFFFFFFFu, k[s], src) & 0xFFFFFFFFULL);
            const float es = g_esq[kk];            // issue early; used after dot
            const float4* e4 = reinterpret_cast<const float4*>(cb + (size_t)kk * DDIM);
            float p = 0.f;
            #pragma unroll
            for (int w8 = 0; w8 < 8; w8++) {
                float4 a = a4[lane + w8 * 32];
                float4 e = e4[lane + w8 * 32];
                p += a.x * e.x + a.y * e.y + a.z * e.z + a.w * e.w;
            }
            #pragma unroll
            for (int o = 16; o > 0; o >>= 1) p += __shfl_xor_sync(0xFFFFFFFFu, p, o);
            float d = es - 2.f * p;
            if (d < bd || (d == bd && kk < bk)) { bd = d; bk = kk; }
        }
    }
    if (lane == 0) s_idx[warp] = bk;
    __syncthreads();                               // all rescore reads of buf done

    // ---- gather: warp w stages values[idx[w]] (coalesced), overwriting buf
    {
        const float4* v4 = reinterpret_cast<const float4*>(values + (size_t)s_idx[warp] * DDIM);
        float4* d4 = reinterpret_cast<float4*>(&buf[warp][0]);
        #pragma unroll
        for (int w8 = 0; w8 < 8; w8++) d4[lane + w8 * 32] = v4[lane + w8 * 32];
    }
    __syncthreads();

    // ---- transposed write: out[b][c][n0+j] = buf[j][c]
    float* ob = out + (size_t)b * (DDIM * NIMG) + n0;
    #pragma unroll
    for (int i = 0; i < 32; i++) {
        int L = threadIdx.x + i * 256;
        int c = L >> 3, j = L & 7;
        ob[(size_t)c * NIMG + j] = buf[j][c];
    }
}

// ---------------------------------------------------------------------------
extern "C" void kernel_launch(void* const* d_in, const int* in_sizes, int n_in,
                              void* d_out, int out_size) {
    const float* x      = (const float*)d_in[0];
    const float* cb     = (const float*)d_in[1];
    const float* values = (const float*)d_in[2];
    float* out          = (float*)d_out;

    static int attr_set = 0;
    if (!attr_set) {
        cudaFuncSetAttribute(gemm_argmin_kernel,
                             cudaFuncAttributeMaxDynamicSharedMemorySize, DYN_SMEM);
        attr_set = 1;
    }

    convert_all_kernel<<<CBBLOCKS + XBLOCKS, dim3(32, 8)>>>(x, cb);

    gemm_argmin_kernel<<<dim3(KCODES / TN, MTOK / TM), 256, DYN_SMEM>>>();

    // rescore launched with programmatic dependent launch: it may begin while
    // the GEMM tail drains; griddepcontrol.wait guards all g_cand reads.
    {
        cudaLaunchConfig_t cfg = {};
        cfg.gridDim = dim3(MTOK / 8);
        cfg.blockDim = dim3(256);
        cfg.dynamicSmemBytes = 0;
        cudaLaunchAttribute at[1];
        at[0].id = cudaLaunchAttributeProgrammaticStreamSerialization;
        at[0].val.programmaticStreamSerializationAllowed = 1;
        cfg.attrs = at;
        cfg.numAttrs = 1;
        cudaLaunchKernelEx(&cfg, rescore_gather_kernel, x, cb, values, out);
    }
}

// round 17
// speedup vs baseline: 1.0591x; 1.0022x over previous
#include <cuda_runtime.h>
#include <cuda_fp16.h>
#include <cstdint>

// ---------------------------------------------------------------------------
// Problem constants
// ---------------------------------------------------------------------------
#define BATCH   16
#define DDIM    1024
#define NIMG    256
#define MTOK    (BATCH * NIMG)   // 4096
#define KCODES  8192
#define NTILES  (KCODES / 128)   // 64 code tiles

// GEMM tiling: fp16, block 128x128, warp 32x64, KC=64 channels (128B rows)
#define TM 128
#define TN 128
#define KC 64
#define NCHUNK (DDIM / KC)       // 16
#define NSTAGE 3

// Dynamic smem layout
#define OFF_A  0
#define OFF_B  16384
#define STAGE  32768
#define ES_OFF   (NSTAGE * STAGE)            // 98304, 128 floats
#define TOP1_OFF (ES_OFF + 512)              // u64 [128][2]
#define TOP2_OFF (TOP1_OFF + 2048)
#define DYN_SMEM (TOP2_OFF + 2048)           // 102912

#define EPS 0.25f

// convert grid split: cb blocks FIRST (longest work first -> better packing)
#define CBBLOCKS (KCODES / 8)                 // 1024
#define XBLOCKS 2048                          // 8 nt x 16 ct x 16 b

// ---------------------------------------------------------------------------
// Global scratch (allocation-free rule: __device__ globals)
// ---------------------------------------------------------------------------
__device__ __half  g_A[MTOK * DDIM];
__device__ __half  g_B[KCODES * DDIM];
__device__ float   g_esq[KCODES];
// interleaved: [token][tile][{top1, top2}]
__device__ unsigned long long g_cand[MTOK * NTILES * 2];

// ---------------------------------------------------------------------------
// Helpers
// ---------------------------------------------------------------------------
__device__ __forceinline__ uint32_t smem_u32(const void* p) {
    uint32_t a;
    asm("{ .reg .u64 t; cvta.to.shared.u64 t, %1; cvt.u32.u64 %0, t; }" : "=r"(a) : "l"(p));
    return a;
}

#define CP_ASYNC16(dst, src) \
    asm volatile("cp.async.cg.shared.global [%0], [%1], 16;\n" :: "r"(dst), "l"(src))
#define CP_COMMIT() asm volatile("cp.async.commit_group;\n" ::: "memory")

#define LDSM4(r0, r1, r2, r3, addr)                                         \
    asm volatile("ldmatrix.sync.aligned.m8n8.x4.shared.b16 {%0,%1,%2,%3}, [%4];" \
                 : "=r"(r0), "=r"(r1), "=r"(r2), "=r"(r3) : "r"(addr))

#define MMA16816(acc, a, b0, b1)                                            \
    asm volatile("mma.sync.aligned.m16n8k16.row.col.f32.f16.f16.f32 "       \
                 "{%0,%1,%2,%3}, {%4,%5,%6,%7}, {%8,%9}, {%0,%1,%2,%3};"    \
                 : "+f"((acc)[0]), "+f"((acc)[1]), "+f"((acc)[2]), "+f"((acc)[3]) \
                 : "r"((a)[0]), "r"((a)[1]), "r"((a)[2]), "r"((a)[3]),      \
                   "r"(b0), "r"(b1))

#define PDL_LAUNCH_DEPENDENTS() \
    asm volatile("griddepcontrol.launch_dependents;" ::: "memory")
#define PDL_WAIT() \
    asm volatile("griddepcontrol.wait;" ::: "memory")

__device__ __forceinline__ unsigned long long pack_key(float d, int k) {
    unsigned u = __float_as_uint(d);
    u = (u & 0x80000000u) ? ~u : (u | 0x80000000u);
    return ((unsigned long long)u << 32) | (unsigned)k;
}
__device__ __forceinline__ float unpack_key_d(unsigned long long key) {
    unsigned u = (unsigned)(key >> 32);
    u = (u & 0x80000000u) ? (u ^ 0x80000000u) : ~u;
    return __uint_as_float(u);
}
__device__ __forceinline__ void upd_top2(unsigned long long& k1, unsigned long long& k2,
                                         unsigned long long key) {
    if (key < k1) { k2 = k1; k1 = key; }
    else if (key < k2) { k2 = key; }
}
__device__ __forceinline__ void merge_top2(unsigned long long& k1, unsigned long long& k2,
                                           unsigned long long o1, unsigned long long o2) {
    if (o1 < k1) { k2 = (k1 < o2) ? k1 : o2; k1 = o1; }
    else if (o1 < k2) { k2 = o1; }
}

// 128-row x 128-byte tile, 16B chunk swizzle: conflict-free for ldmatrix and cp.async
__device__ __forceinline__ uint32_t sw_off128(int row, int chunk) {
    return (uint32_t)(row * 128 + ((chunk ^ (row & 7)) << 4));
}

// ---------------------------------------------------------------------------
// Fused prepass (R14 champion) + early launch_dependents so the GEMM grid
// prelaunches during the convert tail.
// ---------------------------------------------------------------------------
__global__ void convert_all_kernel(const float* __restrict__ x, const float* __restrict__ cb) {
    const int bid = blockIdx.x;
    const int tx = threadIdx.x, ty = threadIdx.y;
    const int tid = ty * 32 + tx;

    PDL_LAUNCH_DEPENDENTS();   // dependents guard with griddepcontrol.wait

    if (bid < CBBLOCKS) {
        const int wid = tid >> 5, lane = tid & 31;
        const int gw = bid * 8 + wid;
        const float4* row = reinterpret_cast<const float4*>(cb + (size_t)gw * DDIM);
        float4 v[8];
        #pragma unroll
        for (int w = 0; w < 8; w++) v[w] = row[lane + w * 32];
        float s = 0.f;
        #pragma unroll
        for (int w = 0; w < 8; w++) {
            s += v[w].x * v[w].x + v[w].y * v[w].y + v[w].z * v[w].z + v[w].w * v[w].w;
            __half2 h01 = __floats2half2_rn(v[w].x, v[w].y);
            __half2 h23 = __floats2half2_rn(v[w].z, v[w].w);
            uint2 pk;
            pk.x = *reinterpret_cast<uint32_t*>(&h01);
            pk.y = *reinterpret_cast<uint32_t*>(&h23);
            *reinterpret_cast<uint2*>(&g_B[(size_t)gw * DDIM + (lane + w * 32) * 4]) = pk;
        }
        #pragma unroll
        for (int o = 16; o > 0; o >>= 1) s += __shfl_xor_sync(0xFFFFFFFFu, s, o);
        if (lane == 0) g_esq[gw] = s;
    } else {
        __shared__ float tile[64][33];
        const int bx = bid - CBBLOCKS;
        const int nt = bx & 7;
        const int ct = (bx >> 3) & 15;
        const int b = bx >> 7;
        const float* src = x + (size_t)b * (DDIM * NIMG) + (size_t)(ct * 64) * NIMG + nt * 32;
        float rv[8];
        #pragma unroll
        for (int r = 0; r < 8; r++) rv[r] = src[(size_t)(ty + 8 * r) * NIMG + tx];
        #pragma unroll
        for (int r = 0; r < 8; r++) tile[ty + 8 * r][tx] = rv[r];
        __syncthreads();
        const int m0 = b * NIMG + nt * 32;
        const int lane = tx;
        #pragma unroll
        for (int it = 0; it < 4; it++) {
            int j = ty + 8 * it;
            float v0 = tile[2 * lane][j];
            float v1 = tile[2 * lane + 1][j];
            __half2 h = __floats2half2_rn(v0, v1);
            *reinterpret_cast<__half2*>(
                &g_A[(size_t)(m0 + j) * DDIM + ct * 64 + 2 * lane]) = h;
        }
    }
}

// ---------------------------------------------------------------------------
// Main GEMM (R14 champion). Setup runs pre-wait (independent); all reads of
// convert outputs (g_esq, g_A, g_B) happen after griddepcontrol.wait.
// ---------------------------------------------------------------------------
__device__ __forceinline__ void load_chunk(uint32_t st, int m0, int k0, int c0, int tid) {
    const __half* aa = g_A;
    const __half* bb = g_B;
    #pragma unroll
    for (int i = 0; i < 4; i++) {
        int vid = tid + i * 256;           // 0..1023 covers 128 rows x 8 x 16B
        int r = vid >> 3, c = vid & 7;
        uint32_t off = sw_off128(r, c);
        CP_ASYNC16(st + OFF_A + off, aa + (size_t)(m0 + r) * DDIM + c0 + c * 8);
        CP_ASYNC16(st + OFF_B + off, bb + (size_t)(k0 + r) * DDIM + c0 + c * 8);
    }
    CP_COMMIT();
}

__global__ __launch_bounds__(256, 2)
void gemm_argmin_kernel() {
    extern __shared__ char dynsm[];
    const int tid = threadIdx.x;
    const int lane = tid & 31;
    const int wid = tid >> 5;
    const int wr = wid & 3;              // M band (32 rows)
    const int wc = wid >> 2;             // N band (64 cols)
    const int bx = blockIdx.x;           // code tile
    const int m0 = blockIdx.y * TM;
    const int k0 = bx * TN;

    const uint32_t smb = smem_u32(dynsm);
    float* s_es = (float*)(dynsm + ES_OFF);
    unsigned long long* s_top1 = (unsigned long long*)(dynsm + TOP1_OFF);
    unsigned long long* s_top2 = (unsigned long long*)(dynsm + TOP2_OFF);

    // ---- independent setup (runs while convert may still be executing)
    const int hi = lane >> 4;            // chunk parity within k-step
    uint32_t baseA[2]; int selA[2];
    #pragma unroll
    for (int mt = 0; mt < 2; mt++) {
        int row = wr * 32 + mt * 16 + (lane & 15);
        baseA[mt] = (uint32_t)(row * 128);
        selA[mt] = row & 7;
    }
    uint32_t baseB[4]; int selB[4];
    #pragma unroll
    for (int g = 0; g < 4; g++) {
        int row = wc * 64 + g * 16 + (lane & 15);
        baseB[g] = (uint32_t)(row * 128);
        selB[g] = row & 7;
    }

    float acc[2][8][4];
    #pragma unroll
    for (int mt = 0; mt < 2; mt++)
        #pragma unroll
        for (int nt = 0; nt < 8; nt++)
            #pragma unroll
            for (int j = 0; j < 4; j++) acc[mt][nt][j] = 0.f;

    // ---- wait for convert's writes, then allow rescore prelaunch
    PDL_WAIT();
    PDL_LAUNCH_DEPENDENTS();

    if (tid < TN) s_es[tid] = g_esq[k0 + tid];

    load_chunk(smb + 0 * STAGE, m0, k0, 0, tid);
    load_chunk(smb + 1 * STAGE, m0, k0, KC, tid);

    int sidx = 0, widx = 2;
    for (int i = 0; i < NCHUNK; i++) {
        // chunk i must be complete; on the last iteration chunk i is itself
        // the most recent pending group, so wait for ALL.
        if (i + 1 < NCHUNK) { asm volatile("cp.async.wait_group 1;\n" ::: "memory"); }
        else               { asm volatile("cp.async.wait_group 0;\n" ::: "memory"); }
        __syncthreads();
        // Prefetch chunk i+2 into the stage consumed in iteration i-1
        // (protected by the sync above). Single barrier per iteration.
        if (i + 2 < NCHUNK) {
            load_chunk(smb + widx * STAGE, m0, k0, (i + 2) * KC, tid);
            widx = (widx == NSTAGE - 1) ? 0 : widx + 1;
        }

        const uint32_t st = smb + sidx * STAGE;
        #pragma unroll
        for (int ks = 0; ks < 4; ks++) {
            const int ck = 2 * ks + hi;
            uint32_t af[2][4];
            #pragma unroll
            for (int mt = 0; mt < 2; mt++)
                LDSM4(af[mt][0], af[mt][1], af[mt][2], af[mt][3],
                      st + OFF_A + baseA[mt] + ((ck ^ selA[mt]) << 4));
            #pragma unroll
            for (int g = 0; g < 4; g++) {
                uint32_t bf[4];
                LDSM4(bf[0], bf[1], bf[2], bf[3],
                      st + OFF_B + baseB[g] + ((ck ^ selB[g]) << 4));
                #pragma unroll
                for (int mt = 0; mt < 2; mt++) {
                    MMA16816(acc[mt][2 * g],     af[mt], bf[0], bf[2]);
                    MMA16816(acc[mt][2 * g + 1], af[mt], bf[1], bf[3]);
                }
            }
        }
        sidx = (sidx == NSTAGE - 1) ? 0 : sidx + 1;
    }

    // ---- epilogue: dist = e_sq - 2*cross, per-row top-2 over this 128-code tile
    unsigned long long t1[4], t2[4];   // [mt*2 + rhalf]
    #pragma unroll
    for (int i = 0; i < 4; i++) { t1[i] = ~0ULL; t2[i] = ~0ULL; }

    #pragma unroll
    for (int nt = 0; nt < 8; nt++) {
        int cl = wc * 64 + nt * 8 + (lane & 3) * 2;
        float e0 = s_es[cl], e1 = s_es[cl + 1];
        int kg = k0 + cl;
        #pragma unroll
        for (int mt = 0; mt < 2; mt++) {
            upd_top2(t1[mt * 2], t2[mt * 2], pack_key(e0 - 2.f * acc[mt][nt][0], kg));
            upd_top2(t1[mt * 2], t2[mt * 2], pack_key(e1 - 2.f * acc[mt][nt][1], kg + 1));
            upd_top2(t1[mt * 2 + 1], t2[mt * 2 + 1], pack_key(e0 - 2.f * acc[mt][nt][2], kg));
            upd_top2(t1[mt * 2 + 1], t2[mt * 2 + 1], pack_key(e1 - 2.f * acc[mt][nt][3], kg + 1));
        }
    }
    #pragma unroll
    for (int i = 0; i < 4; i++) {
        #pragma unroll
        for (int off = 1; off <= 2; off <<= 1) {
            unsigned long long o1 = __shfl_xor_sync(0xFFFFFFFFu, t1[i], off);
            unsigned long long o2 = __shfl_xor_sync(0xFFFFFFFFu, t2[i], off);
            merge_top2(t1[i], t2[i], o1, o2);
        }
    }
    if ((lane & 3) == 0) {
        #pragma unroll
        for (int i = 0; i < 4; i++) {
            int mt = i >> 1, rh = i & 1;
            int rl = wr * 32 + mt * 16 + (lane >> 2) + rh * 8;
            s_top1[rl * 2 + wc] = t1[i];
            s_top2[rl * 2 + wc] = t2[i];
        }
    }
    __syncthreads();
    if (tid < TM) {
        unsigned long long k1 = s_top1[tid * 2], k2 = s_top2[tid * 2];
        merge_top2(k1, k2, s_top1[tid * 2 + 1], s_top2[tid * 2 + 1]);
        // single 16B store of {top1, top2}
        ulonglong2 pr; pr.x = k1; pr.y = k2;
        *reinterpret_cast<ulonglong2*>(
            &g_cand[((size_t)(m0 + tid) * NTILES + bx) * 2]) = pr;
    }
}

// ---------------------------------------------------------------------------
// Fused rescore + gather with PDL: stages x (GEMM-independent) BEFORE
// griddepcontrol.wait, so staging overlaps the GEMM tail wave.
// ---------------------------------------------------------------------------
__global__ __launch_bounds__(256)
void rescore_gather_kernel(const float* __restrict__ x, const float* __restrict__ cb,
                           const float* __restrict__ values, float* __restrict__ out) {
    __shared__ __align__(16) float buf[8][1036];   // 1036 % 32 == 12: conflict-free
    __shared__ int s_idx[8];
    const int warp = threadIdx.x >> 5;
    const int lane = threadIdx.x & 31;
    const int mb = blockIdx.x * 8;                 // 8 consecutive tokens, same batch
    const int b = mb >> 8;
    const int n0 = mb & 255;
    const int m = mb + warp;

    // ---- stage x[b][:, n0:n0+8] -> buf[j][c]  (independent of the GEMM)
    const float* xb = x + (size_t)b * (DDIM * NIMG) + n0;
    #pragma unroll
    for (int i = 0; i < 32; i++) {
        int L = threadIdx.x + i * 256;             // 0..8191
        int c = L >> 3, j = L & 7;
        buf[j][c] = xb[(size_t)c * NIMG + j];
    }

    // ---- wait for the GEMM grid's writes (g_cand) to be visible
    PDL_WAIT();

    const ulonglong2* cp = reinterpret_cast<const ulonglong2*>(&g_cand[(size_t)m * NTILES * 2]);
    ulonglong2 pa = cp[lane];
    ulonglong2 pb = cp[lane + 32];

    unsigned long long k[4] = {pa.x, pb.x, pa.y, pb.y};
    unsigned long long mn = k[0];
    if (k[1] < mn) mn = k[1];
    if (k[2] < mn) mn = k[2];
    if (k[3] < mn) mn = k[3];
    #pragma unroll
    for (int o = 16; o > 0; o >>= 1) {
        unsigned long long t = __shfl_xor_sync(0xFFFFFFFFu, mn, o);
        if (t < mn) mn = t;
    }
    const float thr = unpack_key_d(mn) + EPS;
    __syncthreads();

    float bd = 3.4e38f;
    int bk = 0x7FFFFFFF;
    const float4* a4 = reinterpret_cast<const float4*>(&buf[warp][0]);

    #pragma unroll
    for (int s = 0; s < 4; s++) {
        unsigned msk = __ballot_sync(0xFFFFFFFFu, unpack_key_d(k[s]) <= thr);
        while (msk) {
            int src = __ffs(msk) - 1;
            msk &= msk - 1;
            int kk = (int)(__shfl_sync(0xFFFFFFFFu, k[s], src) & 0xFFFFFFFFULL);
            const float es = g_esq[kk];            // issue early; used after dot
            const float4* e4 = reinterpret_cast<const float4*>(cb + (size_t)kk * DDIM);
            float p = 0.f;
            #pragma unroll
            for (int w8 = 0; w8 < 8; w8++) {
                float4 a = a4[lane + w8 * 32];
                float4 e = e4[lane + w8 * 32];
                p += a.x * e.x + a.y * e.y + a.z * e.z + a.w * e.w;
            }
            #pragma unroll
            for (int o = 16; o > 0; o >>= 1) p += __shfl_xor_sync(0xFFFFFFFFu, p, o);
            float d = es - 2.f * p;
            if (d < bd || (d == bd && kk < bk)) { bd = d; bk = kk; }
        }
    }
    if (lane == 0) s_idx[warp] = bk;
    __syncthreads();                               // all rescore reads of buf done

    // ---- gather: warp w stages values[idx[w]] (coalesced), overwriting buf
    {
        const float4* v4 = reinterpret_cast<const float4*>(values + (size_t)s_idx[warp] * DDIM);
        float4* d4 = reinterpret_cast<float4*>(&buf[warp][0]);
        #pragma unroll
        for (int w8 = 0; w8 < 8; w8++) d4[lane + w8 * 32] = v4[lane + w8 * 32];
    }
    __syncthreads();

    // ---- transposed write: out[b][c][n0+j] = buf[j][c]
    float* ob = out + (size_t)b * (DDIM * NIMG) + n0;
    #pragma unroll
    for (int i = 0; i < 32; i++) {
        int L = threadIdx.x + i * 256;
        int c = L >> 3, j = L & 7;
        ob[(size_t)c * NIMG + j] = buf[j][c];
    }
}

// ---------------------------------------------------------------------------
extern "C" void kernel_launch(void* const* d_in, const int* in_sizes, int n_in,
                              void* d_out, int out_size) {
    const float* x      = (const float*)d_in[0];
    const float* cb     = (const float*)d_in[1];
    const float* values = (const float*)d_in[2];
    float* out          = (float*)d_out;

    static int attr_set = 0;
    if (!attr_set) {
        cudaFuncSetAttribute(gemm_argmin_kernel,
                             cudaFuncAttributeMaxDynamicSharedMemorySize, DYN_SMEM);
        attr_set = 1;
    }

    convert_all_kernel<<<CBBLOCKS + XBLOCKS, dim3(32, 8)>>>(x, cb);

    // GEMM with programmatic dependent launch on convert
    {
        cudaLaunchConfig_t cfg = {};
        cfg.gridDim = dim3(KCODES / TN, MTOK / TM);
        cfg.blockDim = dim3(256);
        cfg.dynamicSmemBytes = DYN_SMEM;
        cudaLaunchAttribute at[1];
        at[0].id = cudaLaunchAttributeProgrammaticStreamSerialization;
        at[0].val.programmaticStreamSerializationAllowed = 1;
        cfg.attrs = at;
        cfg.numAttrs = 1;
        cudaLaunchKernelEx(&cfg, gemm_argmin_kernel);
    }

    // rescore with programmatic dependent launch on the GEMM
    {
        cudaLaunchConfig_t cfg = {};
        cfg.gridDim = dim3(MTOK / 8);
        cfg.blockDim = dim3(256);
        cfg.dynamicSmemBytes = 0;
        cudaLaunchAttribute at[1];
        at[0].id = cudaLaunchAttributeProgrammaticStreamSerialization;
        at[0].val.programmaticStreamSerializationAllowed = 1;
        cfg.attrs = at;
        cfg.numAttrs = 1;
        cudaLaunchKernelEx(&cfg, rescore_gather_kernel, x, cb, values, out);
    }
}